// round 13
// baseline (speedup 1.0000x reference)
#include <cuda_runtime.h>
#include <cuda_fp16.h>
#include <cstdint>

#define T_TOK   4096
#define D_MODEL 1024
#define D_FF    4096
#define NUM_EXP 8
#define BK 32

// ---------------- helpers ----------------
__device__ __forceinline__ uint32_t smem_to_u32(const void* p) {
    uint32_t a;
    asm("{ .reg .u64 t; cvta.to.shared.u64 t, %1; cvt.u32.u64 %0, t; }" : "=r"(a) : "l"(p));
    return a;
}
__device__ __forceinline__ void cp_async16(uint32_t dst, const void* src) {
    asm volatile("cp.async.ca.shared.global [%0], [%1], 16;" :: "r"(dst), "l"(src));
}
__device__ __forceinline__ void cp_commit() { asm volatile("cp.async.commit_group;"); }
template<int N> __device__ __forceinline__ void cp_wait() {
    asm volatile("cp.async.wait_group %0;" :: "n"(N));
}
#define LDM_X4(r0, r1, r2, r3, addr) \
    asm volatile("ldmatrix.sync.aligned.m8n8.x4.shared.b16 {%0,%1,%2,%3}, [%4];" \
        : "=r"(r0), "=r"(r1), "=r"(r2), "=r"(r3) : "r"(addr))
#define LDM_X4_T(r0, r1, r2, r3, addr) \
    asm volatile("ldmatrix.sync.aligned.m8n8.x4.trans.shared.b16 {%0,%1,%2,%3}, [%4];" \
        : "=r"(r0), "=r"(r1), "=r"(r2), "=r"(r3) : "r"(addr))
#define MMA_F16(d, a, b) \
    asm volatile("mma.sync.aligned.m16n8k16.row.col.f32.f16.f16.f32 " \
        "{%0,%1,%2,%3},{%4,%5,%6,%7},{%8,%9},{%0,%1,%2,%3};" \
        : "+f"((d)[0]), "+f"((d)[1]), "+f"((d)[2]), "+f"((d)[3]) \
        : "r"((a)[0]), "r"((a)[1]), "r"((a)[2]), "r"((a)[3]), "r"((b)[0]), "r"((b)[1]))

// ---------------- scratch ----------------
__device__ int      g_cnt[NUM_EXP];
__device__ int      g_idx[NUM_EXP][T_TOK];
__device__ float    g_wt [NUM_EXP][T_TOK];
__device__ __half   g_xh [(size_t)T_TOK * D_MODEL];
__device__ __half   g_h  [(size_t)2 * T_TOK * D_FF];
__device__ __half   g_w1h[(size_t)NUM_EXP * D_MODEL * D_FF];
__device__ __half   g_w2h[(size_t)NUM_EXP * D_FF * D_MODEL];

// inline prefix: base of expert e
__device__ __forceinline__ int expert_base(int e) {
    int b = 0;
#pragma unroll
    for (int i = 0; i < NUM_EXP; i++) if (i < e) b += g_cnt[i];
    return b;
}

// ---------------- small kernels ----------------
__global__ void k_cvt(const float4* __restrict__ src, __half* __restrict__ dst, int n8) {
    int i = blockIdx.x * blockDim.x + threadIdx.x;
    if (i < n8) {
        float4 v0 = src[i * 2], v1 = src[i * 2 + 1];
        __half2 h0 = __floats2half2_rn(v0.x, v0.y);
        __half2 h1 = __floats2half2_rn(v0.z, v0.w);
        __half2 h2 = __floats2half2_rn(v1.x, v1.y);
        __half2 h3 = __floats2half2_rn(v1.z, v1.w);
        uint4 u;
        u.x = *reinterpret_cast<uint32_t*>(&h0);
        u.y = *reinterpret_cast<uint32_t*>(&h1);
        u.z = *reinterpret_cast<uint32_t*>(&h2);
        u.w = *reinterpret_cast<uint32_t*>(&h3);
        *reinterpret_cast<uint4*>(dst + (size_t)i * 8) = u;
    }
}

// router + fused x->fp16 conversion
__global__ void k_router(const float* __restrict__ x, const float* __restrict__ Wg) {
    int warp = (blockIdx.x * blockDim.x + threadIdx.x) >> 5;
    int lane = threadIdx.x & 31;
    if (warp >= T_TOK) return;
    const float2* xr2 = (const float2*)(x + (size_t)warp * D_MODEL);
    __half2* xh2 = (__half2*)(g_xh + (size_t)warp * D_MODEL);
    float acc[NUM_EXP];
#pragma unroll
    for (int e = 0; e < NUM_EXP; e++) acc[e] = 0.f;
    for (int j = lane; j < D_MODEL / 2; j += 32) {
        float2 v = xr2[j];
        xh2[j] = __floats2half2_rn(v.x, v.y);
        const float4* wg4 = (const float4*)(Wg + (size_t)(2 * j) * NUM_EXP);
        float4 a0 = wg4[0], a1 = wg4[1];
        float4 b0 = wg4[2], b1 = wg4[3];
        acc[0] += v.x * a0.x + v.y * b0.x;
        acc[1] += v.x * a0.y + v.y * b0.y;
        acc[2] += v.x * a0.z + v.y * b0.z;
        acc[3] += v.x * a0.w + v.y * b0.w;
        acc[4] += v.x * a1.x + v.y * b1.x;
        acc[5] += v.x * a1.y + v.y * b1.y;
        acc[6] += v.x * a1.z + v.y * b1.z;
        acc[7] += v.x * a1.w + v.y * b1.w;
    }
#pragma unroll
    for (int e = 0; e < NUM_EXP; e++)
#pragma unroll
        for (int off = 16; off > 0; off >>= 1)
            acc[e] += __shfl_xor_sync(0xffffffffu, acc[e], off);
    if (lane == 0) {
        float m = acc[0];
#pragma unroll
        for (int e = 1; e < NUM_EXP; e++) m = fmaxf(m, acc[e]);
        float p[NUM_EXP]; float s = 0.f;
#pragma unroll
        for (int e = 0; e < NUM_EXP; e++) { p[e] = __expf(acc[e] - m); s += p[e]; }
        float inv = 1.f / s;
#pragma unroll
        for (int e = 0; e < NUM_EXP; e++) p[e] *= inv;
        int i1 = 0;
#pragma unroll
        for (int e = 1; e < NUM_EXP; e++) if (p[e] > p[i1]) i1 = e;
        int i2 = (i1 == 0) ? 1 : 0;
#pragma unroll
        for (int e = 0; e < NUM_EXP; e++) if (e != i1 && e != i2 && p[e] > p[i2]) i2 = e;
        float den = 1.f / (p[i1] + p[i2]);
        int s1 = atomicAdd(&g_cnt[i1], 1);
        g_idx[i1][s1] = warp; g_wt[i1][s1] = p[i1] * den;
        int s2 = atomicAdd(&g_cnt[i2], 1);
        g_idx[i2][s2] = warp; g_wt[i2][s2] = p[i2] * den;
    }
}

// ---------------- templated fp16 mma GEMM (expert-group launch) ----------------
// R9-best config: BM=128, BN=256, warp tile 64x64, 1 CTA/SM
// e = e0 + blockIdx.z
// MODE 0: g_h[base+m] = fp16(relu(x_h[g_idx[e][m]] @ W1h + b1))   KTOT=1024, NTOT=4096
// MODE 1: out[tok]   += ((g_h[base+m] @ W2h) + b2[e]) * g_wt[e][m]  (atomic, KTOT=4096, NTOT=1024)
template<int KTOT, int NTOT, int BMt, int BNt, int WMt, int WNt, int MODE>
__global__ __launch_bounds__(256)
void k_mma_gemm(int e0, const float* __restrict__ bias, float* __restrict__ outp) {
    constexpr int NWM = BMt / WMt;
    constexpr int MT = WMt / 16, NT = WNt / 8, NP = WNt / 16;
    constexpr int A_ROW = 80;
    constexpr int B_ROW = BNt * 2 + 16;
    constexpr int A_ST = BMt * A_ROW;
    constexpr int B_ST = BK * B_ROW;
    constexpr int OFF_B = 4 * A_ST;
    constexpr int OFF_BIAS = OFF_B + 4 * B_ST;
    constexpr int APT = BMt * 4 / 256;
    constexpr int BPT = BNt / 64;
    constexpr int BF4 = BNt / 8;

    int e   = e0 + blockIdx.z;
    int cnt = g_cnt[e];
    int m0  = blockIdx.y * BMt;
    if (m0 >= cnt) return;
    int n0  = blockIdx.x * BNt;
    int base = expert_base(e);

    extern __shared__ char smem[];
    uint32_t su = smem_to_u32(smem);
    int tid = threadIdx.x, wid = tid >> 5, lane = tid & 31;

    float* bias_s = (float*)(smem + OFF_BIAS);
    if (tid < BNt) bias_s[tid] = bias[(size_t)e * NTOT + n0 + tid];

    const __half* Bexp = (MODE ? g_w2h : g_w1h) + (size_t)e * KTOT * NTOT + n0;

    const __half* a_src[APT]; uint32_t a_dst[APT];
#pragma unroll
    for (int p = 0; p < APT; p++) {
        int idx = p * 256 + tid;
        int row = idx >> 2, c = idx & 3;
        int slot = m0 + row; if (slot >= cnt) slot = cnt - 1;
        const __half* arow;
        if (MODE == 0) {
            int tok = g_idx[e][slot];
            arow = g_xh + (size_t)tok * KTOT;
        } else {
            arow = g_h + (size_t)(base + slot) * KTOT;
        }
        a_src[p] = arow + c * 8;
        a_dst[p] = su + (uint32_t)(row * A_ROW + c * 16);
    }
    const __half* b_src[BPT]; uint32_t b_dst[BPT];
#pragma unroll
    for (int p = 0; p < BPT; p++) {
        int idx = p * 256 + tid;
        int row = idx / BF4, c = idx % BF4;
        b_src[p] = Bexp + (size_t)row * NTOT + c * 8;
        b_dst[p] = su + OFF_B + (uint32_t)(row * B_ROW + c * 16);
    }

    constexpr int NCH = KTOT / BK;

    auto issue_chunk = [&](int cc) {
        int st = cc & 3;
        uint32_t ash = (uint32_t)(st * A_ST), bsh = (uint32_t)(st * B_ST);
#pragma unroll
        for (int p = 0; p < APT; p++) cp_async16(a_dst[p] + ash, a_src[p] + (size_t)cc * BK);
#pragma unroll
        for (int p = 0; p < BPT; p++) cp_async16(b_dst[p] + bsh, b_src[p] + (size_t)cc * BK * NTOT);
    };

#pragma unroll
    for (int s = 0; s < 3; s++) { issue_chunk(s); cp_commit(); }

    int wm = wid % NWM, wn = wid / NWM;
    int g = lane >> 2, tg = lane & 3;
    uint32_t rowSel = (uint32_t)(lane & 15);
    uint32_t colSel2 = (uint32_t)(((lane >> 4) << 3) * 2);

    float acc[MT][NT][4];
#pragma unroll
    for (int i = 0; i < MT; i++)
#pragma unroll
        for (int j = 0; j < NT; j++)
#pragma unroll
            for (int r = 0; r < 4; r++) acc[i][j][r] = 0.f;

    for (int c = 0; c < NCH; c++) {
        if (c <= NCH - 3) cp_wait<2>();
        else if (c == NCH - 2) cp_wait<1>();
        else cp_wait<0>();
        __syncthreads();
        if (c + 3 < NCH) { issue_chunk(c + 3); cp_commit(); }

        int s = c & 3;
        uint32_t aB = su + (uint32_t)(s * A_ST);
        uint32_t bB = su + OFF_B + (uint32_t)(s * B_ST);
#pragma unroll
        for (int ks = 0; ks < 2; ks++) {
            uint32_t a[MT][4];
#pragma unroll
            for (int mt = 0; mt < MT; mt++) {
                uint32_t addr = aB + (uint32_t)((wm * WMt + mt * 16) + rowSel) * A_ROW
                                   + (uint32_t)(ks * 32) + colSel2;
                LDM_X4(a[mt][0], a[mt][1], a[mt][2], a[mt][3], addr);
            }
            uint32_t b[NT][2];
#pragma unroll
            for (int np = 0; np < NP; np++) {
                uint32_t addr = bB + (uint32_t)(ks * 16 + rowSel) * B_ROW
                                   + (uint32_t)(wn * WNt + np * 16) * 2 + colSel2;
                LDM_X4_T(b[2 * np][0], b[2 * np][1], b[2 * np + 1][0], b[2 * np + 1][1], addr);
            }
#pragma unroll
            for (int mt = 0; mt < MT; mt++)
#pragma unroll
                for (int nt = 0; nt < NT; nt++)
                    MMA_F16(acc[mt][nt], a[mt], b[nt]);
        }
    }

    // ---- epilogue ----
#pragma unroll
    for (int mt = 0; mt < MT; mt++) {
        int m_lo = m0 + wm * WMt + mt * 16 + g;
        int m_hi = m_lo + 8;
        bool v_lo = (m_lo < cnt), v_hi = (m_hi < cnt);
        if (MODE == 0) {
            __half* row_lo = g_h + (size_t)(base + (v_lo ? m_lo : 0)) * D_FF;
            __half* row_hi = g_h + (size_t)(base + (v_hi ? m_hi : 0)) * D_FF;
#pragma unroll
            for (int nt = 0; nt < NT; nt++) {
                int col = n0 + wn * WNt + nt * 8 + tg * 2;
                if (v_lo) {
                    __half2 h = __floats2half2_rn(
                        fmaxf(acc[mt][nt][0] + bias_s[col - n0], 0.f),
                        fmaxf(acc[mt][nt][1] + bias_s[col - n0 + 1], 0.f));
                    *(__half2*)(row_lo + col) = h;
                }
                if (v_hi) {
                    __half2 h = __floats2half2_rn(
                        fmaxf(acc[mt][nt][2] + bias_s[col - n0], 0.f),
                        fmaxf(acc[mt][nt][3] + bias_s[col - n0 + 1], 0.f));
                    *(__half2*)(row_hi + col) = h;
                }
            }
        } else {
            int tok_lo = 0, tok_hi = 0; float w_lo = 0.f, w_hi = 0.f;
            if (v_lo) { tok_lo = g_idx[e][m_lo]; w_lo = g_wt[e][m_lo]; }
            if (v_hi) { tok_hi = g_idx[e][m_hi]; w_hi = g_wt[e][m_hi]; }
            float* row_lo = outp + (size_t)tok_lo * D_MODEL;
            float* row_hi = outp + (size_t)tok_hi * D_MODEL;
#pragma unroll
            for (int nt = 0; nt < NT; nt++) {
                int col = n0 + wn * WNt + nt * 8 + tg * 2;
                float blo = bias_s[col - n0], bhi = bias_s[col - n0 + 1];
                if (v_lo) {
                    atomicAdd(row_lo + col,     (acc[mt][nt][0] + blo) * w_lo);
                    atomicAdd(row_lo + col + 1, (acc[mt][nt][1] + bhi) * w_lo);
                }
                if (v_hi) {
                    atomicAdd(row_hi + col,     (acc[mt][nt][2] + blo) * w_hi);
                    atomicAdd(row_hi + col + 1, (acc[mt][nt][3] + bhi) * w_hi);
                }
            }
        }
    }
}

#define SMEM_GEMM (4 * (128 * 80) + 4 * (BK * (256 * 2 + 16)) + 256 * 4)   // 109568

extern "C" void kernel_launch(void* const* d_in, const int* in_sizes, int n_in,
                              void* d_out, int out_size) {
    const float* x  = (const float*)d_in[0];
    const float* Wg = (const float*)d_in[1];
    const float* W1 = (const float*)d_in[2];
    const float* b1 = (const float*)d_in[3];
    const float* W2 = (const float*)d_in[4];
    const float* b2 = (const float*)d_in[5];
    float* out = (float*)d_out;

    static cudaStream_t s1 = nullptr, s2 = nullptr;
    static cudaEvent_t evRoot = nullptr, evRt = nullptr, evW2 = nullptr,
                       evE1 = nullptr, evE2 = nullptr;
    if (!s1) {
        cudaStreamCreateWithFlags(&s1, cudaStreamNonBlocking);
        cudaStreamCreateWithFlags(&s2, cudaStreamNonBlocking);
        cudaEventCreateWithFlags(&evRoot, cudaEventDisableTiming);
        cudaEventCreateWithFlags(&evRt, cudaEventDisableTiming);
        cudaEventCreateWithFlags(&evW2, cudaEventDisableTiming);
        cudaEventCreateWithFlags(&evE1, cudaEventDisableTiming);
        cudaEventCreateWithFlags(&evE2, cudaEventDisableTiming);
        cudaFuncSetAttribute(k_mma_gemm<D_MODEL, D_FF, 128, 256, 64, 64, 0>,
                             cudaFuncAttributeMaxDynamicSharedMemorySize, SMEM_GEMM);
        cudaFuncSetAttribute(k_mma_gemm<D_FF, D_MODEL, 128, 256, 64, 64, 1>,
                             cudaFuncAttributeMaxDynamicSharedMemorySize, SMEM_GEMM);
    }

    __half* w1h; cudaGetSymbolAddress((void**)&w1h, g_w1h);
    __half* w2h; cudaGetSymbolAddress((void**)&w2h, g_w2h);
    int* cntp;   cudaGetSymbolAddress((void**)&cntp, g_cnt);

    int nWH = NUM_EXP * D_MODEL * D_FF / 2;
    int nH8 = nWH / 8;
    int nW8 = NUM_EXP * D_MODEL * D_FF / 8;

    // zero expert counters and the output accumulator (memsets — not kernel nodes)
    cudaMemsetAsync(cntp, 0, NUM_EXP * sizeof(int), 0);
    cudaMemsetAsync(out, 0, (size_t)T_TOK * D_MODEL * sizeof(float), 0);

    cudaEventRecord(evRoot, 0);
    cudaStreamWaitEvent(s1, evRoot, 0);
    cudaStreamWaitEvent(s2, evRoot, 0);

    // kernel #1/#2: W1 halves on side streams
    k_cvt<<<(nH8 + 255) / 256, 256, 0, s1>>>((const float4*)W1, w1h, nH8);
    k_cvt<<<(nH8 + 255) / 256, 256, 0, s2>>>((const float4*)(W1 + (size_t)nWH), w1h + (size_t)nWH, nH8);

    // kernel #3: router (fused x->fp16) on main
    k_router<<<T_TOK / 8, 256>>>(x, Wg);
    cudaEventRecord(evRt, 0);

    // kernel #4: GEMM1 group A (profiled launch)
    cudaStreamWaitEvent(s1, evRt, 0);
    k_mma_gemm<D_MODEL, D_FF, 128, 256, 64, 64, 0>
        <<<dim3(D_FF / 256, T_TOK / 128, 4), 256, SMEM_GEMM, s1>>>(0, b1, nullptr);

    // kernel #5: W2 convert on main (overlaps GEMM1)
    k_cvt<<<(nW8 + 255) / 256, 256>>>((const float4*)W2, w2h, nW8);
    cudaEventRecord(evW2, 0);

    // kernel #6: GEMM1 group B
    cudaStreamWaitEvent(s2, evRt, 0);
    k_mma_gemm<D_MODEL, D_FF, 128, 256, 64, 64, 0>
        <<<dim3(D_FF / 256, T_TOK / 128, 4), 256, SMEM_GEMM, s2>>>(4, b1, nullptr);

    // GEMM2 groups: fused atomic combine into out
    cudaStreamWaitEvent(s1, evW2, 0);
    k_mma_gemm<D_FF, D_MODEL, 128, 256, 64, 64, 1>
        <<<dim3(D_MODEL / 256, T_TOK / 128, 4), 256, SMEM_GEMM, s1>>>(0, b2, out);
    cudaEventRecord(evE1, s1);

    cudaStreamWaitEvent(s2, evW2, 0);
    k_mma_gemm<D_FF, D_MODEL, 128, 256, 64, 64, 1>
        <<<dim3(D_MODEL / 256, T_TOK / 128, 4), 256, SMEM_GEMM, s2>>>(4, b2, out);
    cudaEventRecord(evE2, s2);

    // rejoin side streams into main before capture ends
    cudaStreamWaitEvent(0, evE1, 0);
    cudaStreamWaitEvent(0, evE2, 0);
}

// round 14
// speedup vs baseline: 1.0278x; 1.0278x over previous
#include <cuda_runtime.h>
#include <cuda_fp16.h>
#include <cstdint>

#define T_TOK   4096
#define D_MODEL 1024
#define D_FF    4096
#define NUM_EXP 8
#define BK 32

// ---------------- helpers ----------------
__device__ __forceinline__ uint32_t smem_to_u32(const void* p) {
    uint32_t a;
    asm("{ .reg .u64 t; cvta.to.shared.u64 t, %1; cvt.u32.u64 %0, t; }" : "=r"(a) : "l"(p));
    return a;
}
__device__ __forceinline__ void cp_async16(uint32_t dst, const void* src) {
    asm volatile("cp.async.ca.shared.global [%0], [%1], 16;" :: "r"(dst), "l"(src));
}
__device__ __forceinline__ void cp_commit() { asm volatile("cp.async.commit_group;"); }
template<int N> __device__ __forceinline__ void cp_wait() {
    asm volatile("cp.async.wait_group %0;" :: "n"(N));
}
#define LDM_X4(r0, r1, r2, r3, addr) \
    asm volatile("ldmatrix.sync.aligned.m8n8.x4.shared.b16 {%0,%1,%2,%3}, [%4];" \
        : "=r"(r0), "=r"(r1), "=r"(r2), "=r"(r3) : "r"(addr))
#define LDM_X4_T(r0, r1, r2, r3, addr) \
    asm volatile("ldmatrix.sync.aligned.m8n8.x4.trans.shared.b16 {%0,%1,%2,%3}, [%4];" \
        : "=r"(r0), "=r"(r1), "=r"(r2), "=r"(r3) : "r"(addr))
#define MMA_F16(d, a, b) \
    asm volatile("mma.sync.aligned.m16n8k16.row.col.f32.f16.f16.f32 " \
        "{%0,%1,%2,%3},{%4,%5,%6,%7},{%8,%9},{%0,%1,%2,%3};" \
        : "+f"((d)[0]), "+f"((d)[1]), "+f"((d)[2]), "+f"((d)[3]) \
        : "r"((a)[0]), "r"((a)[1]), "r"((a)[2]), "r"((a)[3]), "r"((b)[0]), "r"((b)[1]))

// ---------------- scratch ----------------
__device__ int      g_cnt[NUM_EXP];
__device__ int      g_idx[NUM_EXP][T_TOK];
__device__ uint32_t g_tk[2 * T_TOK];
__device__ float    g_tw[2 * T_TOK];
__device__ __half   g_xh [(size_t)T_TOK * D_MODEL];
__device__ __half   g_h  [(size_t)2 * T_TOK * D_FF];
__device__ float    g_y  [(size_t)2 * T_TOK * D_MODEL];
__device__ __half   g_w1h[(size_t)NUM_EXP * D_MODEL * D_FF];
__device__ __half   g_w2h[(size_t)NUM_EXP * D_FF * D_MODEL];

// inline prefix: base of expert e
__device__ __forceinline__ int expert_base(int e) {
    int b = 0;
#pragma unroll
    for (int i = 0; i < NUM_EXP; i++) if (i < e) b += g_cnt[i];
    return b;
}

// ---------------- small kernels ----------------
__global__ void k_cvt(const float4* __restrict__ src, __half* __restrict__ dst, int n8) {
    int i = blockIdx.x * blockDim.x + threadIdx.x;
    if (i < n8) {
        float4 v0 = src[i * 2], v1 = src[i * 2 + 1];
        __half2 h0 = __floats2half2_rn(v0.x, v0.y);
        __half2 h1 = __floats2half2_rn(v0.z, v0.w);
        __half2 h2 = __floats2half2_rn(v1.x, v1.y);
        __half2 h3 = __floats2half2_rn(v1.z, v1.w);
        uint4 u;
        u.x = *reinterpret_cast<uint32_t*>(&h0);
        u.y = *reinterpret_cast<uint32_t*>(&h1);
        u.z = *reinterpret_cast<uint32_t*>(&h2);
        u.w = *reinterpret_cast<uint32_t*>(&h3);
        *reinterpret_cast<uint4*>(dst + (size_t)i * 8) = u;
    }
}

// router + fused x->fp16 conversion
__global__ void k_router(const float* __restrict__ x, const float* __restrict__ Wg) {
    int warp = (blockIdx.x * blockDim.x + threadIdx.x) >> 5;
    int lane = threadIdx.x & 31;
    if (warp >= T_TOK) return;
    const float2* xr2 = (const float2*)(x + (size_t)warp * D_MODEL);
    __half2* xh2 = (__half2*)(g_xh + (size_t)warp * D_MODEL);
    float acc[NUM_EXP];
#pragma unroll
    for (int e = 0; e < NUM_EXP; e++) acc[e] = 0.f;
    for (int j = lane; j < D_MODEL / 2; j += 32) {
        float2 v = xr2[j];
        xh2[j] = __floats2half2_rn(v.x, v.y);
        const float4* wg4 = (const float4*)(Wg + (size_t)(2 * j) * NUM_EXP);
        float4 a0 = wg4[0], a1 = wg4[1];
        float4 b0 = wg4[2], b1 = wg4[3];
        acc[0] += v.x * a0.x + v.y * b0.x;
        acc[1] += v.x * a0.y + v.y * b0.y;
        acc[2] += v.x * a0.z + v.y * b0.z;
        acc[3] += v.x * a0.w + v.y * b0.w;
        acc[4] += v.x * a1.x + v.y * b1.x;
        acc[5] += v.x * a1.y + v.y * b1.y;
        acc[6] += v.x * a1.z + v.y * b1.z;
        acc[7] += v.x * a1.w + v.y * b1.w;
    }
#pragma unroll
    for (int e = 0; e < NUM_EXP; e++)
#pragma unroll
        for (int off = 16; off > 0; off >>= 1)
            acc[e] += __shfl_xor_sync(0xffffffffu, acc[e], off);
    if (lane == 0) {
        float m = acc[0];
#pragma unroll
        for (int e = 1; e < NUM_EXP; e++) m = fmaxf(m, acc[e]);
        float p[NUM_EXP]; float s = 0.f;
#pragma unroll
        for (int e = 0; e < NUM_EXP; e++) { p[e] = __expf(acc[e] - m); s += p[e]; }
        float inv = 1.f / s;
#pragma unroll
        for (int e = 0; e < NUM_EXP; e++) p[e] *= inv;
        int i1 = 0;
#pragma unroll
        for (int e = 1; e < NUM_EXP; e++) if (p[e] > p[i1]) i1 = e;
        int i2 = (i1 == 0) ? 1 : 0;
#pragma unroll
        for (int e = 0; e < NUM_EXP; e++) if (e != i1 && e != i2 && p[e] > p[i2]) i2 = e;
        float den = 1.f / (p[i1] + p[i2]);
        int s1 = atomicAdd(&g_cnt[i1], 1);
        g_idx[i1][s1] = warp;
        int s2 = atomicAdd(&g_cnt[i2], 1);
        g_idx[i2][s2] = warp;
        g_tk[warp * 2]     = ((uint32_t)i1 << 12) | (uint32_t)s1;
        g_tk[warp * 2 + 1] = ((uint32_t)i2 << 12) | (uint32_t)s2;
        g_tw[warp * 2]     = p[i1] * den;
        g_tw[warp * 2 + 1] = p[i2] * den;
    }
}

// ---------------- templated fp16 mma GEMM (expert-group launch) ----------------
// GEMM1 (MODE 0): 128x128 tile, 64x32 warp, 2 CTAs/SM   — measured fastest
// GEMM2 (MODE 1): 128x256 tile, 64x64 warp, 1 CTA/SM    — measured fastest
// e = e0 + blockIdx.z
// MODE 0: g_h[base+m] = fp16(relu(x_h[g_idx[e][m]] @ W1h + b1))
// MODE 1: g_y[base+m] = fp32(g_h[base+m] @ W2h)
template<int KTOT, int NTOT, int BMt, int BNt, int WMt, int WNt, int MODE>
__global__ __launch_bounds__(256, MODE ? 1 : 2)
void k_mma_gemm(int e0, const float* __restrict__ bias) {
    constexpr int NWM = BMt / WMt;
    constexpr int MT = WMt / 16, NT = WNt / 8, NP = WNt / 16;
    constexpr int A_ROW = 80;
    constexpr int B_ROW = BNt * 2 + 16;
    constexpr int A_ST = BMt * A_ROW;
    constexpr int B_ST = BK * B_ROW;
    constexpr int OFF_B = 4 * A_ST;
    constexpr int OFF_BIAS = OFF_B + 4 * B_ST;
    constexpr int APT = BMt * 4 / 256;
    constexpr int BPT = BNt / 64;
    constexpr int BF4 = BNt / 8;

    int e   = e0 + blockIdx.z;
    int cnt = g_cnt[e];
    int m0  = blockIdx.y * BMt;
    if (m0 >= cnt) return;
    int n0  = blockIdx.x * BNt;
    int base = expert_base(e);

    extern __shared__ char smem[];
    uint32_t su = smem_to_u32(smem);
    int tid = threadIdx.x, wid = tid >> 5, lane = tid & 31;

    float* bias_s = (float*)(smem + OFF_BIAS);
    if (MODE == 0 && tid < BNt) bias_s[tid] = bias[(size_t)e * NTOT + n0 + tid];

    const __half* Bexp = (MODE ? g_w2h : g_w1h) + (size_t)e * KTOT * NTOT + n0;

    const __half* a_src[APT]; uint32_t a_dst[APT];
#pragma unroll
    for (int p = 0; p < APT; p++) {
        int idx = p * 256 + tid;
        int row = idx >> 2, c = idx & 3;
        int slot = m0 + row; if (slot >= cnt) slot = cnt - 1;
        const __half* arow;
        if (MODE == 0) {
            int tok = g_idx[e][slot];
            arow = g_xh + (size_t)tok * KTOT;
        } else {
            arow = g_h + (size_t)(base + slot) * KTOT;
        }
        a_src[p] = arow + c * 8;
        a_dst[p] = su + (uint32_t)(row * A_ROW + c * 16);
    }
    const __half* b_src[BPT]; uint32_t b_dst[BPT];
#pragma unroll
    for (int p = 0; p < BPT; p++) {
        int idx = p * 256 + tid;
        int row = idx / BF4, c = idx % BF4;
        b_src[p] = Bexp + (size_t)row * NTOT + c * 8;
        b_dst[p] = su + OFF_B + (uint32_t)(row * B_ROW + c * 16);
    }

    constexpr int NCH = KTOT / BK;

    auto issue_chunk = [&](int cc) {
        int st = cc & 3;
        uint32_t ash = (uint32_t)(st * A_ST), bsh = (uint32_t)(st * B_ST);
#pragma unroll
        for (int p = 0; p < APT; p++) cp_async16(a_dst[p] + ash, a_src[p] + (size_t)cc * BK);
#pragma unroll
        for (int p = 0; p < BPT; p++) cp_async16(b_dst[p] + bsh, b_src[p] + (size_t)cc * BK * NTOT);
    };

#pragma unroll
    for (int s = 0; s < 3; s++) { issue_chunk(s); cp_commit(); }

    int wm = wid % NWM, wn = wid / NWM;
    int g = lane >> 2, tg = lane & 3;
    uint32_t rowSel = (uint32_t)(lane & 15);
    uint32_t colSel2 = (uint32_t)(((lane >> 4) << 3) * 2);

    float acc[MT][NT][4];
#pragma unroll
    for (int i = 0; i < MT; i++)
#pragma unroll
        for (int j = 0; j < NT; j++)
#pragma unroll
            for (int r = 0; r < 4; r++) acc[i][j][r] = 0.f;

    for (int c = 0; c < NCH; c++) {
        if (c <= NCH - 3) cp_wait<2>();
        else if (c == NCH - 2) cp_wait<1>();
        else cp_wait<0>();
        __syncthreads();
        if (c + 3 < NCH) { issue_chunk(c + 3); cp_commit(); }

        int s = c & 3;
        uint32_t aB = su + (uint32_t)(s * A_ST);
        uint32_t bB = su + OFF_B + (uint32_t)(s * B_ST);
#pragma unroll
        for (int ks = 0; ks < 2; ks++) {
            uint32_t a[MT][4];
#pragma unroll
            for (int mt = 0; mt < MT; mt++) {
                uint32_t addr = aB + (uint32_t)((wm * WMt + mt * 16) + rowSel) * A_ROW
                                   + (uint32_t)(ks * 32) + colSel2;
                LDM_X4(a[mt][0], a[mt][1], a[mt][2], a[mt][3], addr);
            }
            uint32_t b[NT][2];
#pragma unroll
            for (int np = 0; np < NP; np++) {
                uint32_t addr = bB + (uint32_t)(ks * 16 + rowSel) * B_ROW
                                   + (uint32_t)(wn * WNt + np * 16) * 2 + colSel2;
                LDM_X4_T(b[2 * np][0], b[2 * np][1], b[2 * np + 1][0], b[2 * np + 1][1], addr);
            }
#pragma unroll
            for (int mt = 0; mt < MT; mt++)
#pragma unroll
                for (int nt = 0; nt < NT; nt++)
                    MMA_F16(acc[mt][nt], a[mt], b[nt]);
        }
    }

    // ---- epilogue ----
#pragma unroll
    for (int mt = 0; mt < MT; mt++) {
        int m_lo = m0 + wm * WMt + mt * 16 + g;
        int m_hi = m_lo + 8;
        bool v_lo = (m_lo < cnt), v_hi = (m_hi < cnt);
        if (MODE == 0) {
            __half* row_lo = g_h + (size_t)(base + (v_lo ? m_lo : 0)) * D_FF;
            __half* row_hi = g_h + (size_t)(base + (v_hi ? m_hi : 0)) * D_FF;
#pragma unroll
            for (int nt = 0; nt < NT; nt++) {
                int col = n0 + wn * WNt + nt * 8 + tg * 2;
                if (v_lo) {
                    __half2 h = __floats2half2_rn(
                        fmaxf(acc[mt][nt][0] + bias_s[col - n0], 0.f),
                        fmaxf(acc[mt][nt][1] + bias_s[col - n0 + 1], 0.f));
                    *(__half2*)(row_lo + col) = h;
                }
                if (v_hi) {
                    __half2 h = __floats2half2_rn(
                        fmaxf(acc[mt][nt][2] + bias_s[col - n0], 0.f),
                        fmaxf(acc[mt][nt][3] + bias_s[col - n0 + 1], 0.f));
                    *(__half2*)(row_hi + col) = h;
                }
            }
        } else {
            float* row_lo = g_y + (size_t)(base + (v_lo ? m_lo : 0)) * D_MODEL;
            float* row_hi = g_y + (size_t)(base + (v_hi ? m_hi : 0)) * D_MODEL;
#pragma unroll
            for (int nt = 0; nt < NT; nt++) {
                int col = n0 + wn * WNt + nt * 8 + tg * 2;
                if (v_lo) {
                    float2 v; v.x = acc[mt][nt][0]; v.y = acc[mt][nt][1];
                    *(float2*)(row_lo + col) = v;
                }
                if (v_hi) {
                    float2 v; v.x = acc[mt][nt][2]; v.y = acc[mt][nt][3];
                    *(float2*)(row_hi + col) = v;
                }
            }
        }
    }
}

__global__ void k_combine(const float* __restrict__ b2, float* __restrict__ out) {
    int t = blockIdx.x, c = threadIdx.x;
    uint32_t p0 = g_tk[t * 2], p1 = g_tk[t * 2 + 1];
    float w0 = g_tw[t * 2], w1 = g_tw[t * 2 + 1];
    int e0 = p0 >> 12, s0 = p0 & 4095;
    int e1 = p1 >> 12, s1 = p1 & 4095;
    int base0 = expert_base(e0), base1 = expert_base(e1);
    const float4* y0 = (const float4*)(g_y + (size_t)(base0 + s0) * D_MODEL);
    const float4* y1 = (const float4*)(g_y + (size_t)(base1 + s1) * D_MODEL);
    const float4* d0 = (const float4*)(b2 + (size_t)e0 * D_MODEL);
    const float4* d1 = (const float4*)(b2 + (size_t)e1 * D_MODEL);
    float4 A = y0[c], B = y1[c], D0 = d0[c], D1 = d1[c], R;
    R.x = w0 * (A.x + D0.x) + w1 * (B.x + D1.x);
    R.y = w0 * (A.y + D0.y) + w1 * (B.y + D1.y);
    R.z = w0 * (A.z + D0.z) + w1 * (B.z + D1.z);
    R.w = w0 * (A.w + D0.w) + w1 * (B.w + D1.w);
    ((float4*)(out + (size_t)t * D_MODEL))[c] = R;
}

// GEMM1: 128x128 → 4*(128*80) + 4*(32*(128*2+16)) + 128*4 = 76288 (2 CTAs/SM)
#define SMEM_G1 (4 * (128 * 80) + 4 * (BK * (128 * 2 + 16)) + 128 * 4)
// GEMM2: 128x256 → 109568 (1 CTA/SM)
#define SMEM_G2 (4 * (128 * 80) + 4 * (BK * (256 * 2 + 16)) + 256 * 4)

extern "C" void kernel_launch(void* const* d_in, const int* in_sizes, int n_in,
                              void* d_out, int out_size) {
    const float* x  = (const float*)d_in[0];
    const float* Wg = (const float*)d_in[1];
    const float* W1 = (const float*)d_in[2];
    const float* b1 = (const float*)d_in[3];
    const float* W2 = (const float*)d_in[4];
    const float* b2 = (const float*)d_in[5];
    float* out = (float*)d_out;

    static cudaStream_t s1 = nullptr, s2 = nullptr;
    static cudaEvent_t evRoot = nullptr, evRt = nullptr, evW2 = nullptr,
                       evE1 = nullptr, evE2 = nullptr;
    if (!s1) {
        cudaStreamCreateWithFlags(&s1, cudaStreamNonBlocking);
        cudaStreamCreateWithFlags(&s2, cudaStreamNonBlocking);
        cudaEventCreateWithFlags(&evRoot, cudaEventDisableTiming);
        cudaEventCreateWithFlags(&evRt, cudaEventDisableTiming);
        cudaEventCreateWithFlags(&evW2, cudaEventDisableTiming);
        cudaEventCreateWithFlags(&evE1, cudaEventDisableTiming);
        cudaEventCreateWithFlags(&evE2, cudaEventDisableTiming);
        cudaFuncSetAttribute(k_mma_gemm<D_MODEL, D_FF, 128, 128, 64, 32, 0>,
                             cudaFuncAttributeMaxDynamicSharedMemorySize, SMEM_G1);
        cudaFuncSetAttribute(k_mma_gemm<D_FF, D_MODEL, 128, 256, 64, 64, 1>,
                             cudaFuncAttributeMaxDynamicSharedMemorySize, SMEM_G2);
    }

    __half* w1h; cudaGetSymbolAddress((void**)&w1h, g_w1h);
    __half* w2h; cudaGetSymbolAddress((void**)&w2h, g_w2h);
    int* cntp;   cudaGetSymbolAddress((void**)&cntp, g_cnt);

    int nWH = NUM_EXP * D_MODEL * D_FF / 2;
    int nH8 = nWH / 8;
    int nW8 = NUM_EXP * D_MODEL * D_FF / 8;

    cudaMemsetAsync(cntp, 0, NUM_EXP * sizeof(int), 0);

    cudaEventRecord(evRoot, 0);
    cudaStreamWaitEvent(s1, evRoot, 0);
    cudaStreamWaitEvent(s2, evRoot, 0);

    // W1 halves on side streams
    k_cvt<<<(nH8 + 255) / 256, 256, 0, s1>>>((const float4*)W1, w1h, nH8);
    k_cvt<<<(nH8 + 255) / 256, 256, 0, s2>>>((const float4*)(W1 + (size_t)nWH), w1h + (size_t)nWH, nH8);

    // router (fused x->fp16) on main
    k_router<<<T_TOK / 8, 256>>>(x, Wg);
    cudaEventRecord(evRt, 0);

    // GEMM1 group A (128x128 tile, 2 CTAs/SM)
    cudaStreamWaitEvent(s1, evRt, 0);
    k_mma_gemm<D_MODEL, D_FF, 128, 128, 64, 32, 0>
        <<<dim3(D_FF / 128, T_TOK / 128, 4), 256, SMEM_G1, s1>>>(0, b1);

    // W2 convert on main (overlaps GEMM1)
    k_cvt<<<(nW8 + 255) / 256, 256>>>((const float4*)W2, w2h, nW8);
    cudaEventRecord(evW2, 0);

    // GEMM1 group B
    cudaStreamWaitEvent(s2, evRt, 0);
    k_mma_gemm<D_MODEL, D_FF, 128, 128, 64, 32, 0>
        <<<dim3(D_FF / 128, T_TOK / 128, 4), 256, SMEM_G1, s2>>>(4, b1);

    // GEMM2 groups (128x256 tile, write g_y)
    cudaStreamWaitEvent(s1, evW2, 0);
    k_mma_gemm<D_FF, D_MODEL, 128, 256, 64, 64, 1>
        <<<dim3(D_MODEL / 256, T_TOK / 128, 4), 256, SMEM_G2, s1>>>(0, b2);
    cudaEventRecord(evE1, s1);

    cudaStreamWaitEvent(s2, evW2, 0);
    k_mma_gemm<D_FF, D_MODEL, 128, 256, 64, 64, 1>
        <<<dim3(D_MODEL / 256, T_TOK / 128, 4), 256, SMEM_G2, s2>>>(4, b2);
    cudaEventRecord(evE2, s2);

    // combine joins both groups on main
    cudaStreamWaitEvent(0, evE1, 0);
    cudaStreamWaitEvent(0, evE2, 0);
    k_combine<<<T_TOK, 256>>>(b2, out);
}